// round 1
// baseline (speedup 1.0000x reference)
#include <cuda_runtime.h>

#define FRAME 2048

// ---- device-global lag tables (computed per launch by a tiny setup kernel) ----
__device__ float g_lag[2048];
__device__ int   g_flo[2048];
__device__ int   g_cei[2048];

__global__ void lag_table_kernel(int M) {
    int m = blockIdx.x * blockDim.x + threadIdx.x;
    if (m >= M || m >= 2048) return;
    // replicate: midi = np.arange(5, 84, 0.05).astype(float32);
    //            lag  = (22050 / (440 * 2**((float64(midi32)-69)/12))).astype(float32)
    double midi64 = 5.0 + (double)m * 0.05;
    float  midi32 = (float)midi64;
    double e      = ((double)midi32 - 69.0) / 12.0;
    double lag64  = 22050.0 / (440.0 * exp2(e));
    float  lag32  = (float)lag64;
    g_lag[m] = lag32;
    g_flo[m] = (int)floorf(lag32);
    g_cei[m] = (int)ceilf(lag32);
}

// One CTA = one frame. 256 threads.
__global__ __launch_bounds__(256) void yin_kernel(
    const float* __restrict__ x, float* __restrict__ y, int M)
{
    __shared__ float xs[FRAME + 16];     // linear copy (+zero pad)
    __shared__ float xs2[8][264];        // de-interleaved: xs2[b][p] = x[8p+b]; cols 256,257 = 0
    __shared__ float ss[FRAME + 1];      // prefix sum of squares: ss[i] = sum_{n<i} x[n]^2
    __shared__ float d0s[FRAME];         // final normalized difference function d0
    __shared__ float warpAgg[8];

    const int t    = threadIdx.x;
    const int lane = t & 31;
    const int wid  = t >> 5;
    const float* xf = x + (size_t)blockIdx.x * FRAME;

    // ---- load x: linear copy + de-interleaved copy ----
    float4 v0 = ((const float4*)xf)[t];
    float4 v1 = ((const float4*)xf)[t + 256];
    ((float4*)xs)[t]       = v0;
    ((float4*)xs)[t + 256] = v1;
    if (t < 16) xs[FRAME + t] = 0.f;
    {
        int i0 = 4 * t;
        xs2[(i0 + 0) & 7][(i0 + 0) >> 3] = v0.x;
        xs2[(i0 + 1) & 7][(i0 + 1) >> 3] = v0.y;
        xs2[(i0 + 2) & 7][(i0 + 2) >> 3] = v0.z;
        xs2[(i0 + 3) & 7][(i0 + 3) >> 3] = v0.w;
        int i1 = 1024 + 4 * t;
        xs2[(i1 + 0) & 7][(i1 + 0) >> 3] = v1.x;
        xs2[(i1 + 1) & 7][(i1 + 1) >> 3] = v1.y;
        xs2[(i1 + 2) & 7][(i1 + 2) >> 3] = v1.z;
        xs2[(i1 + 3) & 7][(i1 + 3) >> 3] = v1.w;
    }
    if (t < 16) xs2[t & 7][256 + (t >> 3)] = 0.f;
    __syncthreads();

    // ---- scan 1: prefix sum of squares -> ss[0..2048] ----
    {
        float pr[8];
        float run = 0.f;
#pragma unroll
        for (int j = 0; j < 8; j++) {
            float xv = xs[8 * t + j];
            run += xv * xv;
            pr[j] = run;
        }
        float ts = run, sc = run;
#pragma unroll
        for (int off = 1; off < 32; off <<= 1) {
            float o = __shfl_up_sync(0xffffffffu, sc, off);
            if (lane >= off) sc += o;
        }
        if (lane == 31) warpAgg[wid] = sc;
        __syncthreads();
        float wOff = 0.f;
#pragma unroll
        for (int w = 0; w < 8; w++) if (w < wid) wOff += warpAgg[w];
        float tOff = wOff + sc - ts;
#pragma unroll
        for (int j = 0; j < 8; j++) ss[8 * t + j + 1] = tOff + pr[j];
        if (t == 0) ss[0] = 0.f;
        __syncthreads();
    }

    // ---- phase C: autocorrelation, 8 consecutive lags per thread ----
    // acc[d] = r[8t + d] = sum_n xs[n] * xs[n + 8t + d]
    const int k0 = 8 * t;
    float acc[8];
#pragma unroll
    for (int d = 0; d < 8; d++) acc[d] = 0.f;
    {
        float w[16];
        int q = t;
#pragma unroll
        for (int b = 0; b < 8; b++) {
            w[b]     = xs2[b][q];
            w[b + 8] = xs2[b][q + 1];
        }
        const int trips = 256 - t;
        for (int it = 0; it < trips; ++it) {
            const int n = it * 8;
            float4 A0 = *(const float4*)&xs[n];
            float4 A1 = *(const float4*)&xs[n + 4];
            float xn[8] = {A0.x, A0.y, A0.z, A0.w, A1.x, A1.y, A1.z, A1.w};
#pragma unroll
            for (int a = 0; a < 8; a++) {
#pragma unroll
                for (int d = 0; d < 8; d++) {
                    acc[d] = fmaf(xn[a], w[a + d], acc[d]);
                }
            }
            // slide the window by 8
#pragma unroll
            for (int b = 0; b < 8; b++) w[b] = w[b + 8];
#pragma unroll
            for (int b = 0; b < 8; b++) w[b + 8] = xs2[b][q + 2];
            q += 1;
        }
    }

    // ---- raw difference function d_raw[k] = ss[W-k] + (ss[W]-ss[k]) - 2 r[k] ----
    float dr[8];
    {
        float sW = ss[FRAME];
#pragma unroll
        for (int j = 0; j < 8; j++) {
            int k = k0 + j;
            dr[j] = ss[FRAME - k] + (sW - ss[k]) - 2.f * acc[j];
        }
    }
    if (t == 0) dr[0] = 0.f;   // lag 0 excluded from cumsum; d0[0] forced to 1 below
    __syncthreads();           // protect warpAgg reuse

    // ---- scan 2: cumsum of d_raw over lags, then normalize ----
    {
        float pr[8];
        float run = 0.f;
#pragma unroll
        for (int j = 0; j < 8; j++) { run += dr[j]; pr[j] = run; }
        float ts = run, sc = run;
#pragma unroll
        for (int off = 1; off < 32; off <<= 1) {
            float o = __shfl_up_sync(0xffffffffu, sc, off);
            if (lane >= off) sc += o;
        }
        if (lane == 31) warpAgg[wid] = sc;
        __syncthreads();
        float wOff = 0.f;
#pragma unroll
        for (int w = 0; w < 8; w++) if (w < wid) wOff += warpAgg[w];
        float tOff = wOff + sc - ts;
#pragma unroll
        for (int j = 0; j < 8; j++) {
            int k = k0 + j;
            float cum = tOff + pr[j];                 // sum_{lag<=k} d_raw
            float val = (float)k * dr[j] / (cum + 1e-7f);
            d0s[k] = (k == 0) ? 1.0f : val;
        }
    }
    __syncthreads();

    // ---- epilogue: fractional-lag linear interpolation gather ----
    float* yo = y + (size_t)blockIdx.x * M;
    for (int m = t; m < M; m += 256) {
        float lag = g_lag[m];
        int fi = g_flo[m], ci = g_cei[m];
        float dfl = d0s[fi], dce = d0s[ci];
        float numer = (lag - (float)fi) * (dce - dfl);
        float denom = (float)(ci - fi);
        yo[m] = numer / denom + dfl;   // matches reference exactly (incl. 0/0 case)
    }
}

extern "C" void kernel_launch(void* const* d_in, const int* in_sizes, int n_in,
                              void* d_out, int out_size) {
    const float* x = (const float*)d_in[0];
    int total = in_sizes[0];
    int B = total / FRAME;
    int M = out_size / B;
    lag_table_kernel<<<(M + 255) / 256, 256>>>(M);
    yin_kernel<<<B, 256>>>(x, (float*)d_out, M);
}

// round 2
// speedup vs baseline: 4.1282x; 4.1282x over previous
#include <cuda_runtime.h>

#define FRAME 2048
#define NC    2048                        // C2C FFT size
#define IDX(i) ((i) ^ (((i) >> 4) & 15))  // bank-conflict swizzle (bijective per 2048)

// ---- device-global lag tables ----
__device__ float g_lag[2048];
__device__ int   g_flo[2048];
__device__ int   g_cei[2048];

__global__ void lag_table_kernel(int M) {
    int m = blockIdx.x * blockDim.x + threadIdx.x;
    if (m >= M || m >= 2048) return;
    double midi64 = 5.0 + (double)m * 0.05;
    float  midi32 = (float)midi64;
    double e      = ((double)midi32 - 69.0) / 12.0;
    double lag64  = 22050.0 / (440.0 * exp2(e));
    float  lag32  = (float)lag64;
    g_lag[m] = lag32;
    g_flo[m] = (int)floorf(lag32);
    g_cei[m] = (int)ceilf(lag32);
}

__device__ __forceinline__ float2 cmul(float2 a, float2 b) {
    return make_float2(fmaf(a.x, b.x, -a.y * b.y), fmaf(a.x, b.y, a.y * b.x));
}
__device__ __forceinline__ float2 cadd(float2 a, float2 b) { return make_float2(a.x + b.x, a.y + b.y); }
__device__ __forceinline__ float2 csub(float2 a, float2 b) { return make_float2(a.x - b.x, a.y - b.y); }

// ---- Stockham stages (autosort, ping-pong). 2048 = 2 * 4^5 ----
template<bool INV>
__device__ __forceinline__ void stage_r2(const float2* in, float2* out, int t) {
#pragma unroll
    for (int u = 0; u < 4; u++) {
        int j = t + 256 * u;                 // Ns = 1: no twiddle
        float2 a = in[IDX(j)];
        float2 b = in[IDX(j + 1024)];
        out[IDX(2 * j)]     = cadd(a, b);
        out[IDX(2 * j + 1)] = csub(a, b);
    }
    __syncthreads();
}

template<int NS, bool INV>
__device__ __forceinline__ void stage_r4(const float2* in, float2* out, int t) {
#pragma unroll
    for (int u = 0; u < 2; u++) {
        int j  = t + 256 * u;
        int jm = j & (NS - 1);
        float2 v0 = in[IDX(j)];
        float2 v1 = in[IDX(j + 512)];
        float2 v2 = in[IDX(j + 1024)];
        float2 v3 = in[IDX(j + 1536)];
        float s, c;
        sincospif((float)jm * (1.0f / (2.0f * NS)), &s, &c);  // angle/pi, exact dyadic arg
        if (!INV) s = -s;
        float2 w1 = make_float2(c, s);
        float2 w2 = cmul(w1, w1);
        float2 w3 = cmul(w2, w1);
        v1 = cmul(v1, w1); v2 = cmul(v2, w2); v3 = cmul(v3, w3);
        float2 a0 = cadd(v0, v2), a1 = csub(v0, v2);
        float2 a2 = cadd(v1, v3), a3 = csub(v1, v3);
        float2 y0 = cadd(a0, a2), y2 = csub(a0, a2);
        float2 y1, y3;
        if (!INV) {  // y1 = a1 - i*a3 ; y3 = a1 + i*a3
            y1 = make_float2(a1.x + a3.y, a1.y - a3.x);
            y3 = make_float2(a1.x - a3.y, a1.y + a3.x);
        } else {
            y1 = make_float2(a1.x - a3.y, a1.y + a3.x);
            y3 = make_float2(a1.x + a3.y, a1.y - a3.x);
        }
        int base = (j / NS) * (4 * NS) + jm;
        out[IDX(base)]          = y0;
        out[IDX(base + NS)]     = y1;
        out[IDX(base + 2 * NS)] = y2;
        out[IDX(base + 3 * NS)] = y3;
    }
    __syncthreads();
}

template<bool INV>
__device__ __forceinline__ void fft2048(float2* A, float2* B, int t) {
    stage_r2<INV>(A, B, t);
    stage_r4<2,   INV>(B, A, t);
    stage_r4<8,   INV>(A, B, t);
    stage_r4<32,  INV>(B, A, t);
    stage_r4<128, INV>(A, B, t);
    stage_r4<512, INV>(B, A, t);   // result back in A
}

// One CTA = one frame, 256 threads.
__global__ __launch_bounds__(256) void yin_fft_kernel(
    const float* __restrict__ x, float* __restrict__ y, int M)
{
    __shared__ float2 bufA[NC];
    __shared__ float2 bufB[NC];
    __shared__ float  ss[FRAME + 1];
    __shared__ float  warpAgg[8];

    const int t    = threadIdx.x;
    const int lane = t & 31;
    const int wid  = t >> 5;
    const float* xf = x + (size_t)blockIdx.x * FRAME;

    // ---- load x[8t..8t+7] ----
    float4 va = ((const float4*)xf)[2 * t];
    float4 vb = ((const float4*)xf)[2 * t + 1];
    float xr[8] = {va.x, va.y, va.z, va.w, vb.x, vb.y, vb.z, vb.w};

    // ---- pack z[m] = x[2m] + i x[2m+1] (zero-padded upper half) into bufA ----
#pragma unroll
    for (int q = 0; q < 4; q++)
        bufA[IDX(4 * t + q)] = make_float2(xr[2 * q], xr[2 * q + 1]);
#pragma unroll
    for (int q = 0; q < 4; q++)
        bufA[IDX(1024 + 4 * t + q)] = make_float2(0.f, 0.f);

    // ---- scan 1: prefix sum of squares -> ss[0..2048] ----
    {
        float pr[8];
        float run = 0.f;
#pragma unroll
        for (int j = 0; j < 8; j++) { run += xr[j] * xr[j]; pr[j] = run; }
        float ts = run, sc = run;
#pragma unroll
        for (int off = 1; off < 32; off <<= 1) {
            float o = __shfl_up_sync(0xffffffffu, sc, off);
            if (lane >= off) sc += o;
        }
        if (lane == 31) warpAgg[wid] = sc;
        __syncthreads();
        float wOff = 0.f;
#pragma unroll
        for (int w = 0; w < 8; w++) if (w < wid) wOff += warpAgg[w];
        float tOff = wOff + sc - ts;
#pragma unroll
        for (int j = 0; j < 8; j++) ss[8 * t + j + 1] = tOff + pr[j];
        if (t == 0) ss[0] = 0.f;
        __syncthreads();
    }

    // ---- forward C2C 2048: Z in bufA ----
    fft2048<false>(bufA, bufB, t);

    // ---- unpack rfft + power spectrum S[0..2048] into bufB floats ----
    float* s_spec = (float*)bufB;
    {
#pragma unroll
        for (int i = 0; i < 4; i++) {
            int k = t + 256 * i;                     // k in [0,1024)
            float2 Za = bufA[IDX(k)];
            float2 Zb = bufA[IDX((2048 - k) & 2047)];
            float hex = 0.5f * (Za.x + Zb.x), hey = 0.5f * (Za.y - Zb.y);
            float hox = 0.5f * (Za.y + Zb.y), hoy = -0.5f * (Za.x - Zb.x);
            float s, c;
            sincospif((float)k * (1.0f / 2048.0f), &s, &c);   // tw = e^{-i pi k/2048} = (c,-s)
            float ux = c * hox + s * hoy;
            float uy = c * hoy - s * hox;
            float ax = hex + ux, ay = hey + uy;               // H[k]
            float bx = hex - ux, by = hey - uy;               // conj-mirror H[2048-k]
            s_spec[k]        = ax * ax + ay * ay;
            s_spec[2048 - k] = bx * bx + by * by;
        }
        if (t == 0) {
            float2 Za = bufA[IDX(1024)];
            s_spec[1024] = Za.x * Za.x + Za.y * Za.y;
        }
    }
    __syncthreads();

    // ---- pack irfft input: Wp[k] = (A + iB)/2 into bufA ----
#pragma unroll
    for (int i = 0; i < 8; i++) {
        int k = t + 256 * i;
        float Sk = s_spec[k], Sm = s_spec[2048 - k];
        float A  = Sk + Sm, dS = Sk - Sm;
        float s, c;
        sincospif((float)k * (1.0f / 2048.0f), &s, &c);       // e^{+i pi k/2048} = (c,s)
        bufA[IDX(k)] = make_float2(0.5f * (A - s * dS), 0.5f * (c * dS));
    }
    __syncthreads();

    // ---- inverse C2C 2048 (sign +): Wsum in bufA; r[2m]=Re/2048, r[2m+1]=Im/2048 ----
    fft2048<true>(bufA, bufB, t);

    // ---- d_raw[k] = ss[W-k] + (ss[W]-ss[k]) - 2 r[k], 8 lags per thread ----
    const int k0 = 8 * t;
    float dr[8];
    {
        float sW = ss[FRAME];
        const float inv = 1.0f / 2048.0f;
#pragma unroll
        for (int q = 0; q < 4; q++) {
            float2 wv = bufA[IDX(4 * t + q)];
            float r0 = wv.x * inv, r1 = wv.y * inv;
            int k = k0 + 2 * q;
            dr[2 * q]     = ss[FRAME - k]     + (sW - ss[k])     - 2.f * r0;
            dr[2 * q + 1] = ss[FRAME - k - 1] + (sW - ss[k + 1]) - 2.f * r1;
        }
    }
    if (t == 0) dr[0] = 0.f;

    // ---- scan 2: cumsum of d_raw over lags, normalize -> d0s (reuse bufB) ----
    float* d0s = (float*)bufB;
    {
        float pr[8];
        float run = 0.f;
#pragma unroll
        for (int j = 0; j < 8; j++) { run += dr[j]; pr[j] = run; }
        float ts = run, sc = run;
#pragma unroll
        for (int off = 1; off < 32; off <<= 1) {
            float o = __shfl_up_sync(0xffffffffu, sc, off);
            if (lane >= off) sc += o;
        }
        if (lane == 31) warpAgg[wid] = sc;
        __syncthreads();
        float wOff = 0.f;
#pragma unroll
        for (int w = 0; w < 8; w++) if (w < wid) wOff += warpAgg[w];
        float tOff = wOff + sc - ts;
#pragma unroll
        for (int j = 0; j < 8; j++) {
            int k = k0 + j;
            float cum = tOff + pr[j];
            float val = (float)k * dr[j] / (cum + 1e-7f);
            d0s[k] = (k == 0) ? 1.0f : val;
        }
    }
    __syncthreads();

    // ---- epilogue: fractional-lag linear interpolation gather ----
    float* yo = y + (size_t)blockIdx.x * M;
    for (int m = t; m < M; m += 256) {
        float lag = g_lag[m];
        int fi = g_flo[m], ci = g_cei[m];
        float dfl = d0s[fi], dce = d0s[ci];
        float numer = (lag - (float)fi) * (dce - dfl);
        float denom = (float)(ci - fi);
        yo[m] = numer / denom + dfl;
    }
}

extern "C" void kernel_launch(void* const* d_in, const int* in_sizes, int n_in,
                              void* d_out, int out_size) {
    const float* x = (const float*)d_in[0];
    int total = in_sizes[0];
    int B = total / FRAME;
    int M = out_size / B;
    lag_table_kernel<<<(M + 255) / 256, 256>>>(M);
    yin_fft_kernel<<<B, 256>>>(x, (float*)d_out, M);
}

// round 3
// speedup vs baseline: 5.2748x; 1.2777x over previous
#include <cuda_runtime.h>

#define FRAME 2048
#define NC    2048
#define IDX(i) ((i) ^ (((i) >> 4) & 15))  // bank-conflict swizzle (bijective on 11 bits)

// ---- device-global lag tables ----
__device__ float g_lag[2048];
__device__ int   g_flo[2048];
__device__ int   g_cei[2048];

__global__ void lag_table_kernel(int M) {
    int m = blockIdx.x * blockDim.x + threadIdx.x;
    if (m >= M || m >= 2048) return;
    double midi64 = 5.0 + (double)m * 0.05;
    float  midi32 = (float)midi64;
    double e      = ((double)midi32 - 69.0) / 12.0;
    double lag64  = 22050.0 / (440.0 * exp2(e));
    float  lag32  = (float)lag64;
    g_lag[m] = lag32;
    g_flo[m] = (int)floorf(lag32);
    g_cei[m] = (int)ceilf(lag32);
}

__device__ __forceinline__ float2 cmul(float2 a, float2 b) {
    return make_float2(fmaf(a.x, b.x, -a.y * b.y), fmaf(a.x, b.y, a.y * b.x));
}
__device__ __forceinline__ float2 cadd(float2 a, float2 b) { return make_float2(a.x + b.x, a.y + b.y); }
__device__ __forceinline__ float2 csub(float2 a, float2 b) { return make_float2(a.x - b.x, a.y - b.y); }

template<bool INV>
__device__ __forceinline__ void dft4(float2 a, float2 b, float2 c, float2 d, float2* o) {
    float2 p = cadd(a, c), m = csub(a, c);
    float2 q = cadd(b, d), n = csub(b, d);
    o[0] = cadd(p, q);
    o[2] = csub(p, q);
    if (!INV) { o[1] = make_float2(m.x + n.y, m.y - n.x); o[3] = make_float2(m.x - n.y, m.y + n.x); }
    else      { o[1] = make_float2(m.x - n.y, m.y + n.x); o[3] = make_float2(m.x + n.y, m.y - n.x); }
}

// ---- radix-8 Stockham stage: 256 threads, 1 butterfly each ----
template<int NS, bool INV>
__device__ __forceinline__ void stage_r8(const float2* in, float2* out, int t) {
    float2 v[8];
#pragma unroll
    for (int k = 0; k < 8; k++) v[k] = in[IDX(t + 256 * k)];
    const int jm = t & (NS - 1);
    if (NS > 1) {
        float s, c;
        sincospif((float)jm * (1.0f / (4.0f * NS)), &s, &c);  // 2*pi*jm/(8*NS)
        if (!INV) s = -s;
        float2 w1 = make_float2(c, s);
        float2 w2 = cmul(w1, w1);
        float2 w3 = cmul(w1, w2);
        float2 w4 = cmul(w2, w2);
        float2 w5 = cmul(w2, w3);
        float2 w6 = cmul(w3, w3);
        float2 w7 = cmul(w3, w4);
        v[1] = cmul(v[1], w1); v[2] = cmul(v[2], w2); v[3] = cmul(v[3], w3);
        v[4] = cmul(v[4], w4); v[5] = cmul(v[5], w5); v[6] = cmul(v[6], w6);
        v[7] = cmul(v[7], w7);
    }
    // DFT-8 = even/odd DFT-4 + omega_8^k combine
    float2 E[4], O[4];
    dft4<INV>(v[0], v[2], v[4], v[6], E);
    dft4<INV>(v[1], v[3], v[5], v[7], O);
    const float s2 = 0.70710678118654752f;
    float2 o0 = O[0], o1, o2, o3;
    if (!INV) {
        o1 = make_float2(s2 * (O[1].x + O[1].y), s2 * (O[1].y - O[1].x));   // *e^{-i pi/4}
        o2 = make_float2(O[2].y, -O[2].x);                                   // *(-i)
        o3 = make_float2(s2 * (O[3].y - O[3].x), -s2 * (O[3].x + O[3].y));   // *e^{-3i pi/4}
    } else {
        o1 = make_float2(s2 * (O[1].x - O[1].y), s2 * (O[1].y + O[1].x));    // *e^{+i pi/4}
        o2 = make_float2(-O[2].y, O[2].x);                                   // *(+i)
        o3 = make_float2(-s2 * (O[3].x + O[3].y), s2 * (O[3].x - O[3].y));   // *e^{+3i pi/4}
    }
    const int base = (t / NS) * (8 * NS) + jm;
    out[IDX(base)]          = cadd(E[0], o0);
    out[IDX(base + 4 * NS)] = csub(E[0], o0);
    out[IDX(base + 1 * NS)] = cadd(E[1], o1);
    out[IDX(base + 5 * NS)] = csub(E[1], o1);
    out[IDX(base + 2 * NS)] = cadd(E[2], o2);
    out[IDX(base + 6 * NS)] = csub(E[2], o2);
    out[IDX(base + 3 * NS)] = cadd(E[3], o3);
    out[IDX(base + 7 * NS)] = csub(E[3], o3);
    __syncthreads();
}

// ---- final radix-4 stage, NS=512, 2 butterflies per thread ----
template<bool INV>
__device__ __forceinline__ void stage_r4_512(const float2* in, float2* out, int t) {
#pragma unroll
    for (int u = 0; u < 2; u++) {
        int j  = t + 256 * u;          // j in [0,512) == jm
        float2 v0 = in[IDX(j)];
        float2 v1 = in[IDX(j + 512)];
        float2 v2 = in[IDX(j + 1024)];
        float2 v3 = in[IDX(j + 1536)];
        float s, c;
        sincospif((float)j * (1.0f / 1024.0f), &s, &c);
        if (!INV) s = -s;
        float2 w1 = make_float2(c, s);
        float2 w2 = cmul(w1, w1);
        float2 w3 = cmul(w2, w1);
        v1 = cmul(v1, w1); v2 = cmul(v2, w2); v3 = cmul(v3, w3);
        float2 a0 = cadd(v0, v2), a1 = csub(v0, v2);
        float2 a2 = cadd(v1, v3), a3 = csub(v1, v3);
        float2 y0 = cadd(a0, a2), y2 = csub(a0, a2);
        float2 y1, y3;
        if (!INV) {
            y1 = make_float2(a1.x + a3.y, a1.y - a3.x);
            y3 = make_float2(a1.x - a3.y, a1.y + a3.x);
        } else {
            y1 = make_float2(a1.x - a3.y, a1.y + a3.x);
            y3 = make_float2(a1.x + a3.y, a1.y - a3.x);
        }
        out[IDX(j)]        = y0;
        out[IDX(j + 512)]  = y1;
        out[IDX(j + 1024)] = y2;
        out[IDX(j + 1536)] = y3;
    }
    __syncthreads();
}

// full 2048 C2C: stages X->Y->X->Y->X ; result lands in X
template<bool INV>
__device__ __forceinline__ void fft2048(float2* X, float2* Y, int t) {
    stage_r8<1,  INV>(X, Y, t);
    stage_r8<8,  INV>(Y, X, t);
    stage_r8<64, INV>(X, Y, t);
    stage_r4_512<INV>(Y, X, t);
}

// One CTA = one frame, 256 threads.
__global__ __launch_bounds__(256, 3) void yin_fft_kernel(
    const float* __restrict__ x, float* __restrict__ y, int M)
{
    __shared__ float2 bufA[NC];
    __shared__ float2 bufB[NC];
    __shared__ float  ss[FRAME + 1];
    __shared__ float  warpAgg[8];

    const int t    = threadIdx.x;
    const int lane = t & 31;
    const int wid  = t >> 5;
    const float* xf = x + (size_t)blockIdx.x * FRAME;

    // ---- load x[8t..8t+7], pack z[m] = x[2m] + i x[2m+1], zero upper half ----
    float4 va = ((const float4*)xf)[2 * t];
    float4 vb = ((const float4*)xf)[2 * t + 1];
    float xr[8] = {va.x, va.y, va.z, va.w, vb.x, vb.y, vb.z, vb.w};
#pragma unroll
    for (int q = 0; q < 4; q++)
        bufA[IDX(4 * t + q)] = make_float2(xr[2 * q], xr[2 * q + 1]);
#pragma unroll
    for (int q = 0; q < 4; q++)
        bufA[IDX(1024 + 4 * t + q)] = make_float2(0.f, 0.f);

    // ---- scan 1: prefix sum of squares -> ss[0..2048] ----
    {
        float pr[8];
        float run = 0.f;
#pragma unroll
        for (int j = 0; j < 8; j++) { run += xr[j] * xr[j]; pr[j] = run; }
        float ts = run, sc = run;
#pragma unroll
        for (int off = 1; off < 32; off <<= 1) {
            float o = __shfl_up_sync(0xffffffffu, sc, off);
            if (lane >= off) sc += o;
        }
        if (lane == 31) warpAgg[wid] = sc;
        __syncthreads();
        float wOff = 0.f;
#pragma unroll
        for (int w = 0; w < 8; w++) if (w < wid) wOff += warpAgg[w];
        float tOff = wOff + sc - ts;
#pragma unroll
        for (int j = 0; j < 8; j++) ss[8 * t + j + 1] = tOff + pr[j];
        if (t == 0) ss[0] = 0.f;
        __syncthreads();
    }

    // ---- forward C2C 2048: Z -> bufA ----
    fft2048<false>(bufA, bufB, t);

    // ---- FUSED: unpack rfft -> power spectrum -> irfft packing, bufA -> bufB ----
    // For each k in [0,1024): compute H[k], H[2048-k]; S_k, S_{2048-k};
    // write Wp[k] = 0.5*(A - s*dS, c*dS)  and  Wp[2048-k] = 0.5*(A + s*dS, c*dS)
    // where A = S_k + S_m, dS = S_k - S_m, (c,s) = e^{i pi k/2048}.
    {
#pragma unroll
        for (int i = 0; i < 4; i++) {
            int k = t + 256 * i;                     // k in [0,1024)
            float2 Za = bufA[IDX(k)];
            float2 Zb = bufA[IDX((2048 - k) & 2047)];
            float hex = 0.5f * (Za.x + Zb.x), hey = 0.5f * (Za.y - Zb.y);
            float hox = 0.5f * (Za.y + Zb.y), hoy = -0.5f * (Za.x - Zb.x);
            float s, c;
            sincospif((float)k * (1.0f / 2048.0f), &s, &c);
            float ux = c * hox + s * hoy;            // tw = e^{-i pi k/2048} applied to Ho
            float uy = c * hoy - s * hox;
            float ax = hex + ux, ay = hey + uy;      // H[k]
            float bx = hex - ux, by = hey - uy;      // H[2048-k] (k=0: H[2048])
            float Sk = ax * ax + ay * ay;
            float Sm = bx * bx + by * by;
            float A  = Sk + Sm, dS = Sk - Sm;
            bufB[IDX(k)] = make_float2(0.5f * (A - s * dS), 0.5f * (c * dS));
            if (k > 0)
                bufB[IDX(2048 - k)] = make_float2(0.5f * (A + s * dS), 0.5f * (c * dS));
        }
        if (t == 0) {
            float2 Zn = bufA[IDX(1024)];
            bufB[IDX(1024)] = make_float2(Zn.x * Zn.x + Zn.y * Zn.y, 0.f);
        }
    }
    __syncthreads();

    // ---- inverse C2C 2048: Wp -> bufB ; r[2m]=Re/2048, r[2m+1]=Im/2048 ----
    fft2048<true>(bufB, bufA, t);

    // ---- d_raw[k] = ss[W-k] + (ss[W]-ss[k]) - 2 r[k], 8 lags per thread ----
    const int k0 = 8 * t;
    float dr[8];
    {
        float sW = ss[FRAME];
        const float inv = 1.0f / 2048.0f;
#pragma unroll
        for (int q = 0; q < 4; q++) {
            float2 wv = bufB[IDX(4 * t + q)];
            float r0 = wv.x * inv, r1 = wv.y * inv;
            int k = k0 + 2 * q;
            dr[2 * q]     = ss[FRAME - k]     + (sW - ss[k])     - 2.f * r0;
            dr[2 * q + 1] = ss[FRAME - k - 1] + (sW - ss[k + 1]) - 2.f * r1;
        }
    }
    if (t == 0) dr[0] = 0.f;
    __syncthreads();   // protect warpAgg + bufA reuse

    // ---- scan 2: cumsum over lags, normalize -> d0s (reuse bufA) ----
    float* d0s = (float*)bufA;
    {
        float pr[8];
        float run = 0.f;
#pragma unroll
        for (int j = 0; j < 8; j++) { run += dr[j]; pr[j] = run; }
        float ts = run, sc = run;
#pragma unroll
        for (int off = 1; off < 32; off <<= 1) {
            float o = __shfl_up_sync(0xffffffffu, sc, off);
            if (lane >= off) sc += o;
        }
        if (lane == 31) warpAgg[wid] = sc;
        __syncthreads();
        float wOff = 0.f;
#pragma unroll
        for (int w = 0; w < 8; w++) if (w < wid) wOff += warpAgg[w];
        float tOff = wOff + sc - ts;
#pragma unroll
        for (int j = 0; j < 8; j++) {
            int k = k0 + j;
            float cum = tOff + pr[j];
            float val = (float)k * dr[j] / (cum + 1e-7f);
            d0s[k] = (k == 0) ? 1.0f : val;
        }
    }
    __syncthreads();

    // ---- epilogue: fractional-lag linear interpolation gather ----
    float* yo = y + (size_t)blockIdx.x * M;
    for (int m = t; m < M; m += 256) {
        float lag = g_lag[m];
        int fi = g_flo[m], ci = g_cei[m];
        float dfl = d0s[fi], dce = d0s[ci];
        float numer = (lag - (float)fi) * (dce - dfl);
        float denom = (float)(ci - fi);
        yo[m] = numer / denom + dfl;
    }
}

extern "C" void kernel_launch(void* const* d_in, const int* in_sizes, int n_in,
                              void* d_out, int out_size) {
    const float* x = (const float*)d_in[0];
    int total = in_sizes[0];
    int B = total / FRAME;
    int M = out_size / B;
    lag_table_kernel<<<(M + 255) / 256, 256>>>(M);
    yin_fft_kernel<<<B, 256>>>(x, (float*)d_out, M);
}

// round 5
// speedup vs baseline: 5.8814x; 1.1150x over previous
#include <cuda_runtime.h>

#define FRAME 2048
#define IDX(i) ((i) ^ (((i) >> 4) & 15))   // float2 FFT-buffer swizzle
#define SSW(i) ((i) ^ (((i) >> 5) & 31))   // float scan-array swizzle (kills stride-8 conflicts)

// ---- device-global lag tables ----
__device__ float g_lag[2048];
__device__ int   g_flo[2048];
__device__ int   g_cei[2048];

__global__ void lag_table_kernel(int M) {
    int m = blockIdx.x * blockDim.x + threadIdx.x;
    if (m >= M || m >= 2048) return;
    double midi64 = 5.0 + (double)m * 0.05;
    float  midi32 = (float)midi64;
    double e      = ((double)midi32 - 69.0) / 12.0;
    double lag64  = 22050.0 / (440.0 * exp2(e));
    float  lag32  = (float)lag64;
    g_lag[m] = lag32;
    g_flo[m] = (int)floorf(lag32);
    g_cei[m] = (int)ceilf(lag32);
}

__device__ __forceinline__ float2 cmul(float2 a, float2 b) {
    return make_float2(fmaf(a.x, b.x, -a.y * b.y), fmaf(a.x, b.y, a.y * b.x));
}
__device__ __forceinline__ float2 cadd(float2 a, float2 b) { return make_float2(a.x + b.x, a.y + b.y); }
__device__ __forceinline__ float2 csub(float2 a, float2 b) { return make_float2(a.x - b.x, a.y - b.y); }

template<bool INV>
__device__ __forceinline__ void dft4(float2 a, float2 b, float2 c, float2 d, float2* o) {
    float2 p = cadd(a, c), m = csub(a, c);
    float2 q = cadd(b, d), n = csub(b, d);
    o[0] = cadd(p, q);
    o[2] = csub(p, q);
    if (!INV) { o[1] = make_float2(m.x + n.y, m.y - n.x); o[3] = make_float2(m.x - n.y, m.y + n.x); }
    else      { o[1] = make_float2(m.x - n.y, m.y + n.x); o[3] = make_float2(m.x + n.y, m.y - n.x); }
}

// ---- omega_8 combine shared by radix-8 stages ----
template<bool INV>
__device__ __forceinline__ void omega8(const float2* O, float2& o1, float2& o2, float2& o3) {
    const float s2 = 0.70710678118654752f;
    if (!INV) {
        o1 = make_float2(s2 * (O[1].x + O[1].y), s2 * (O[1].y - O[1].x));   // *e^{-i pi/4}
        o2 = make_float2(O[2].y, -O[2].x);                                   // *(-i)
        o3 = make_float2(s2 * (O[3].y - O[3].x), -s2 * (O[3].x + O[3].y));   // *e^{-3i pi/4}
    } else {
        o1 = make_float2(s2 * (O[1].x - O[1].y), s2 * (O[1].y + O[1].x));
        o2 = make_float2(-O[2].y, O[2].x);
        o3 = make_float2(-s2 * (O[3].x + O[3].y), s2 * (O[3].x - O[3].y));
    }
}

// ---- generic radix-8 Stockham stage (smem -> smem) ----
// load identity: IDX(t + 256k) == tld + 256k  (mask bits 0-3 disjoint from 256k) — valid
template<int NS, bool INV>
__device__ __forceinline__ void stage_r8(const float2* in, float2* out, int t, int tld) {
    float2 v[8];
#pragma unroll
    for (int k = 0; k < 8; k++) v[k] = in[tld + 256 * k];
    const int jm = t & (NS - 1);
    if (NS > 1) {
        float s, c;
        sincospif((float)jm * (1.0f / (4.0f * NS)), &s, &c);
        if (!INV) s = -s;
        float2 w1 = make_float2(c, s);
        v[1] = cmul(v[1], w1);
        float2 w2 = cmul(w1, w1);
        v[2] = cmul(v[2], w2);
        float2 w3 = cmul(w2, w1);
        v[3] = cmul(v[3], w3);
        float2 w4 = cmul(w2, w2);
        v[4] = cmul(v[4], w4);
        v[5] = cmul(v[5], cmul(w4, w1));
        v[6] = cmul(v[6], cmul(w4, w2));
        v[7] = cmul(v[7], cmul(w4, w3));
    }
    float2 E[4], O[4];
    dft4<INV>(v[0], v[2], v[4], v[6], E);
    dft4<INV>(v[1], v[3], v[5], v[7], O);
    float2 o1, o2, o3;
    omega8<INV>(O, o1, o2, o3);
    const int base = (t / NS) * (8 * NS) + jm;
    out[IDX(base)]          = cadd(E[0], O[0]);
    out[IDX(base + 4 * NS)] = csub(E[0], O[0]);
    out[IDX(base + 1 * NS)] = cadd(E[1], o1);
    out[IDX(base + 5 * NS)] = csub(E[1], o1);
    out[IDX(base + 2 * NS)] = cadd(E[2], o2);
    out[IDX(base + 6 * NS)] = csub(E[2], o2);
    out[IDX(base + 3 * NS)] = cadd(E[3], o3);
    out[IDX(base + 7 * NS)] = csub(E[3], o3);
    __syncthreads();
}

// ---- forward stage 1 (NS=1): reads 4 nonzero inputs from GLOBAL, v[4..7]=0 ----
__device__ __forceinline__ void stage1_fwd_zero(const float2* gx, float2* out, int t) {
    float2 v0 = gx[t], v1 = gx[t + 256], v2 = gx[t + 512], v3 = gx[t + 768];
    float2 E[4], O[4];
    E[0] = cadd(v0, v2);
    E[2] = csub(v0, v2);
    E[1] = make_float2(v0.x + v2.y, v0.y - v2.x);   // v0 - i v2
    E[3] = make_float2(v0.x - v2.y, v0.y + v2.x);   // v0 + i v2
    O[0] = cadd(v1, v3);
    O[2] = csub(v1, v3);
    O[1] = make_float2(v1.x + v3.y, v1.y - v3.x);
    O[3] = make_float2(v1.x - v3.y, v1.y + v3.x);
    float2 o1, o2, o3;
    omega8<false>(O, o1, o2, o3);
    const int b = 8 * t;                            // per-element IDX (mask overlaps low bits)
    out[IDX(b + 0)] = cadd(E[0], O[0]);
    out[IDX(b + 4)] = csub(E[0], O[0]);
    out[IDX(b + 1)] = cadd(E[1], o1);
    out[IDX(b + 5)] = csub(E[1], o1);
    out[IDX(b + 2)] = cadd(E[2], o2);
    out[IDX(b + 6)] = csub(E[2], o2);
    out[IDX(b + 3)] = cadd(E[3], o3);
    out[IDX(b + 7)] = csub(E[3], o3);
    __syncthreads();
}

// ---- final radix-4 stage (NS=512); STORE_ALL=false drops outputs >= 1024 ----
// identities IDX(j) == jb and IDX(j + 512m) == jb + 512m are valid (512m above mask bits)
template<bool INV, bool STORE_ALL>
__device__ __forceinline__ void stage_r4_512(const float2* in, float2* out, int t, int tld) {
#pragma unroll
    for (int u = 0; u < 2; u++) {
        int j  = t + 256 * u;
        int jb = tld + 256 * u;
        float2 v0 = in[jb];
        float2 v1 = in[jb + 512];
        float2 v2 = in[jb + 1024];
        float2 v3 = in[jb + 1536];
        float s, c;
        sincospif((float)j * (1.0f / 1024.0f), &s, &c);
        if (!INV) s = -s;
        float2 w1 = make_float2(c, s);
        float2 w2 = cmul(w1, w1);
        float2 w3 = cmul(w2, w1);
        v1 = cmul(v1, w1); v2 = cmul(v2, w2); v3 = cmul(v3, w3);
        float2 a0 = cadd(v0, v2), a1 = csub(v0, v2);
        float2 a2 = cadd(v1, v3), a3 = csub(v1, v3);
        out[jb] = cadd(a0, a2);
        float2 y1 = (!INV) ? make_float2(a1.x + a3.y, a1.y - a3.x)
                           : make_float2(a1.x - a3.y, a1.y + a3.x);
        out[jb + 512] = y1;
        if (STORE_ALL) {
            out[jb + 1024] = csub(a0, a2);
            float2 y3 = (!INV) ? make_float2(a1.x - a3.y, a1.y + a3.x)
                               : make_float2(a1.x + a3.y, a1.y - a3.x);
            out[jb + 1536] = y3;
        }
    }
    __syncthreads();
}

// One CTA = one frame, 256 threads.
__global__ __launch_bounds__(256, 4) void yin_fft_kernel(
    const float* __restrict__ x, float* __restrict__ y, int M)
{
    __shared__ float2 bufA[2048];
    __shared__ float2 bufB[2048];
    __shared__ float  ss[2049];
    __shared__ float  warpAgg[8];

    const int t    = threadIdx.x;
    const int lane = t & 31;
    const int wid  = t >> 5;
    const int tld  = t ^ ((t >> 4) & 15);   // == IDX(t)
    const float* xf = x + (size_t)blockIdx.x * FRAME;

    // ---- scan 1: prefix sum of squares -> ss[0..2048] (swizzled) ----
    {
        float4 va = ((const float4*)xf)[2 * t];
        float4 vb = ((const float4*)xf)[2 * t + 1];
        float xr[8] = {va.x, va.y, va.z, va.w, vb.x, vb.y, vb.z, vb.w};
        float pr[8];
        float run = 0.f;
#pragma unroll
        for (int j = 0; j < 8; j++) { run += xr[j] * xr[j]; pr[j] = run; }
        float ts = run, sc = run;
#pragma unroll
        for (int off = 1; off < 32; off <<= 1) {
            float o = __shfl_up_sync(0xffffffffu, sc, off);
            if (lane >= off) sc += o;
        }
        if (lane == 31) warpAgg[wid] = sc;
        __syncthreads();
        float wOff = 0.f;
#pragma unroll
        for (int w = 0; w < 8; w++) if (w < wid) wOff += warpAgg[w];
        float tOff = wOff + sc - ts;
#pragma unroll
        for (int j = 0; j < 8; j++) ss[SSW(8 * t + j + 1)] = tOff + pr[j];
        if (t == 0) ss[SSW(0)] = 0.f;
        __syncthreads();
    }

    // ---- forward C2C 2048 (input: z[m]=x[2m]+ix[2m+1], upper half zero) ----
    stage1_fwd_zero((const float2*)xf, bufA, t);          // G -> A
    stage_r8<8,  false>(bufA, bufB, t, tld);              // A -> B
    stage_r8<64, false>(bufB, bufA, t, tld);              // B -> A
    stage_r4_512<false, true>(bufA, bufB, t, tld);        // A -> B   (Z in B)

    // ---- FUSED: unpack rfft -> power spectrum -> irfft pack, B -> A ----
    {
#pragma unroll
        for (int i = 0; i < 4; i++) {
            int k = t + 256 * i;                          // k in [0,1024)
            float2 Za = bufB[IDX(k)];
            float2 Zb = bufB[IDX((2048 - k) & 2047)];
            float hex = 0.5f * (Za.x + Zb.x), hey = 0.5f * (Za.y - Zb.y);
            float hox = 0.5f * (Za.y + Zb.y), hoy = -0.5f * (Za.x - Zb.x);
            float s, c;
            sincospif((float)k * (1.0f / 2048.0f), &s, &c);
            float ux = c * hox + s * hoy;
            float uy = c * hoy - s * hox;
            float ax = hex + ux, ay = hey + uy;           // H[k]
            float bx = hex - ux, by = hey - uy;           // H[2048-k]
            float Sk = ax * ax + ay * ay;
            float Sm = bx * bx + by * by;
            float A  = Sk + Sm, dS = Sk - Sm;
            bufA[IDX(k)] = make_float2(0.5f * (A - s * dS), 0.5f * (c * dS));
            if (k > 0)
                bufA[IDX(2048 - k)] = make_float2(0.5f * (A + s * dS), 0.5f * (c * dS));
        }
        if (t == 0) {
            float2 Zn = bufB[IDX(1024)];
            bufA[IDX(1024)] = make_float2(Zn.x * Zn.x + Zn.y * Zn.y, 0.f);
        }
    }
    __syncthreads();

    // ---- inverse C2C 2048 (only outputs [0,1024) needed at the end) ----
    stage_r8<1,  true>(bufA, bufB, t, tld);               // A -> B
    stage_r8<8,  true>(bufB, bufA, t, tld);               // B -> A
    stage_r8<64, true>(bufA, bufB, t, tld);               // A -> B
    stage_r4_512<true, false>(bufB, bufA, t, tld);        // B -> A (half store)

    // ---- d_raw[k] = ss[W-k] + (ss[W]-ss[k]) - 2 r[k] ----
    const int k0 = 8 * t;
    float dr[8];
    {
        float sW = ss[SSW(2048)];
        const float inv = 1.0f / 2048.0f;
#pragma unroll
        for (int q = 0; q < 4; q++) {
            float2 wv = bufA[IDX(4 * t + q)];             // per-element IDX (mask overlaps q)
            float r0 = wv.x * inv, r1 = wv.y * inv;
            int k = k0 + 2 * q;
            dr[2 * q]     = ss[SSW(FRAME - k)]     + (sW - ss[SSW(k)])     - 2.f * r0;
            dr[2 * q + 1] = ss[SSW(FRAME - k - 1)] + (sW - ss[SSW(k + 1)]) - 2.f * r1;
        }
    }
    if (t == 0) dr[0] = 0.f;
    __syncthreads();   // protect warpAgg + bufB reuse

    // ---- scan 2: cumsum over lags, normalize -> d0s (reuse bufB, swizzled) ----
    float* d0s = (float*)bufB;
    {
        float pr[8];
        float run = 0.f;
#pragma unroll
        for (int j = 0; j < 8; j++) { run += dr[j]; pr[j] = run; }
        float ts = run, sc = run;
#pragma unroll
        for (int off = 1; off < 32; off <<= 1) {
            float o = __shfl_up_sync(0xffffffffu, sc, off);
            if (lane >= off) sc += o;
        }
        if (lane == 31) warpAgg[wid] = sc;
        __syncthreads();
        float wOff = 0.f;
#pragma unroll
        for (int w = 0; w < 8; w++) if (w < wid) wOff += warpAgg[w];
        float tOff = wOff + sc - ts;
#pragma unroll
        for (int j = 0; j < 8; j++) {
            int k = k0 + j;
            float cum = tOff + pr[j];
            float val = (float)k * dr[j] / (cum + 1e-7f);
            d0s[SSW(k)] = (k == 0) ? 1.0f : val;
        }
    }
    __syncthreads();

    // ---- epilogue: fractional-lag linear interpolation gather ----
    float* yo = y + (size_t)blockIdx.x * M;
    for (int m = t; m < M; m += 256) {
        float lag = g_lag[m];
        int fi = g_flo[m], ci = g_cei[m];
        float dfl = d0s[SSW(fi)], dce = d0s[SSW(ci)];
        float numer = (lag - (float)fi) * (dce - dfl);
        float denom = (float)(ci - fi);
        yo[m] = numer / denom + dfl;
    }
}

extern "C" void kernel_launch(void* const* d_in, const int* in_sizes, int n_in,
                              void* d_out, int out_size) {
    const float* x = (const float*)d_in[0];
    int total = in_sizes[0];
    int B = total / FRAME;
    int M = out_size / B;
    lag_table_kernel<<<(M + 255) / 256, 256>>>(M);
    yin_fft_kernel<<<B, 256>>>(x, (float*)d_out, M);
}